// round 2
// baseline (speedup 1.0000x reference)
#include <cuda_runtime.h>
#include <cstdint>

// Problem dims (fixed by reference)
#define BSZ 4
#define SSZ 2048
#define DSZ 1024
#define HN  16
#define AD  64
#define HID 1024   // HN*AD

// ---------------- scratch (no allocs allowed) ----------------
__device__ float g_q[(size_t)BSZ * HN * SSZ * AD];   // [B,H,S,AD]
__device__ float g_k[(size_t)BSZ * HN * SSZ * AD];
__device__ float g_v[(size_t)BSZ * HN * SSZ * AD];
__device__ float g_o[(size_t)BSZ * SSZ * HID];       // [B,S,HID]

// ============================================================
// Kernel 1: QKV projection.  C[m,n] = sum_k A[m,k] * Wa[n,k]
// A = iQ [M=8192, K=1024] row-major, Wa [N=3072, K=1024] row-major.
// Epilogue scatters into head-major g_q/g_k/g_v.
// Tile: BM=BN=128, BK=16, 256 threads, 8x8 per thread.
// ============================================================
__global__ void __launch_bounds__(256) gemm_qkv_kernel(
    const float* __restrict__ A, const float* __restrict__ W)
{
    __shared__ float As[16][128];
    __shared__ float Ws[16][128];

    const int bm = blockIdx.y * 128;
    const int bn = blockIdx.x * 128;
    const int tid = threadIdx.x;
    const int tx = tid & 15;       // 0..15 -> n sub-tile
    const int ty = tid >> 4;       // 0..15 -> m sub-tile

    float acc[8][8];
    #pragma unroll
    for (int i = 0; i < 8; i++)
        #pragma unroll
        for (int j = 0; j < 8; j++) acc[i][j] = 0.f;

    for (int k0 = 0; k0 < DSZ; k0 += 16) {
        #pragma unroll
        for (int it = 0; it < 2; it++) {
            int lin = tid + it * 256;          // 0..511 float4 slots
            int row = lin >> 2;                // 0..127
            int kq  = (lin & 3) << 2;          // 0,4,8,12
            float4 a = *(const float4*)(A + (size_t)(bm + row) * DSZ + k0 + kq);
            As[kq + 0][row] = a.x; As[kq + 1][row] = a.y;
            As[kq + 2][row] = a.z; As[kq + 3][row] = a.w;
            float4 w = *(const float4*)(W + (size_t)(bn + row) * DSZ + k0 + kq);
            Ws[kq + 0][row] = w.x; Ws[kq + 1][row] = w.y;
            Ws[kq + 2][row] = w.z; Ws[kq + 3][row] = w.w;
        }
        __syncthreads();
        #pragma unroll
        for (int k = 0; k < 16; k++) {
            float ar[8], br[8];
            *(float4*)(ar)     = *(const float4*)&As[k][ty * 8];
            *(float4*)(ar + 4) = *(const float4*)&As[k][ty * 8 + 4];
            *(float4*)(br)     = *(const float4*)&Ws[k][tx * 8];
            *(float4*)(br + 4) = *(const float4*)&Ws[k][tx * 8 + 4];
            #pragma unroll
            for (int i = 0; i < 8; i++)
                #pragma unroll
                for (int j = 0; j < 8; j++)
                    acc[i][j] += ar[i] * br[j];
        }
        __syncthreads();
    }

    // scatter epilogue: n in [0,3072): which = n/1024 (q/k/v), head = (n%1024)/64
    const int n0 = bn + tx * 8;                 // multiple of 8, stays within one head
    const int which = n0 >> 10;
    const int r  = n0 & 1023;
    const int h  = r >> 6;
    const int d0 = r & 63;
    float* tgt = (which == 0) ? g_q : ((which == 1) ? g_k : g_v);

    #pragma unroll
    for (int i = 0; i < 8; i++) {
        int m = bm + ty * 8 + i;
        int b = m >> 11;
        int s = m & 2047;
        float* dst = tgt + (((size_t)(b * HN + h) * SSZ + s) * AD + d0);
        *(float4*)(dst)     = *(const float4*)&acc[i][0];
        *(float4*)(dst + 4) = *(const float4*)&acc[i][4];
    }
}

// ============================================================
// Kernel 2: masked flash attention.
// grid = (S/128, B*H); 128 threads; 1 q-row per thread.
// Streams K/V in 32-row smem tiles; online softmax in registers.
// Mask is int32 per element (numpy bool widened by the harness).
// ============================================================
#define TS 32

__global__ void __launch_bounds__(128) attn_kernel(const unsigned int* __restrict__ mask)
{
    __shared__ float Ks[TS][AD];
    __shared__ float Vs[TS][AD];

    const int bh = blockIdx.y;           // 0..63
    const int b  = bh >> 4;
    const int h  = bh & 15;
    const int q  = blockIdx.x * 128 + threadIdx.x;   // q row in [0,2048)

    const float* qp    = g_q + ((size_t)bh * SSZ + q) * AD;
    const float* kbase = g_k + (size_t)bh * SSZ * AD;
    const float* vbase = g_v + (size_t)bh * SSZ * AD;
    const unsigned int* mrow = mask + ((size_t)b * SSZ + q) * SSZ;

    // load + pre-scale q by 1/sqrt(64)
    float qf[AD];
    {
        const float4* q4 = (const float4*)qp;
        #pragma unroll
        for (int i = 0; i < 16; i++) {
            float4 t = q4[i];
            qf[4*i+0] = t.x * 0.125f; qf[4*i+1] = t.y * 0.125f;
            qf[4*i+2] = t.z * 0.125f; qf[4*i+3] = t.w * 0.125f;
        }
    }

    float o[AD];
    #pragma unroll
    for (int d = 0; d < AD; d++) o[d] = 0.f;
    float mx = -1e30f, l = 0.f;

    for (int t0 = 0; t0 < SSZ; t0 += TS) {
        __syncthreads();   // protect previous tile reads
        // cooperative load of K/V tiles: 512 float4 slots each half
        #pragma unroll
        for (int it = 0; it < 4; it++) {
            int lin = threadIdx.x + it * 128;   // 0..511
            int rr = lin >> 4;                  // 0..31
            int c4 = (lin & 15) << 2;           // 0..60
            *(float4*)&Ks[rr][c4] = *(const float4*)&kbase[(size_t)(t0 + rr) * AD + c4];
            *(float4*)&Vs[rr][c4] = *(const float4*)&vbase[(size_t)(t0 + rr) * AD + c4];
        }
        __syncthreads();

        // mask ints for this thread's q row: 32 int32 = 8 uint4 loads
        unsigned int marr[TS];
        #pragma unroll
        for (int i = 0; i < 8; i++)
            *(uint4*)&marr[4 * i] = *(const uint4*)(mrow + t0 + 4 * i);

        // scores
        float s[TS];
        #pragma unroll
        for (int j = 0; j < TS; j++) {
            const float4* k4 = (const float4*)Ks[j];
            float a0 = 0.f, a1 = 0.f, a2 = 0.f, a3 = 0.f;
            #pragma unroll
            for (int d = 0; d < 16; d++) {
                float4 kv = k4[d];
                a0 += qf[4*d+0] * kv.x;
                a1 += qf[4*d+1] * kv.y;
                a2 += qf[4*d+2] * kv.z;
                a3 += qf[4*d+3] * kv.w;
            }
            float sj = (a0 + a1) + (a2 + a3);
            s[j] = marr[j] ? -1e30f : sj;   // mask==true -> -inf-ish
        }

        // online softmax update
        float mx_new = mx;
        #pragma unroll
        for (int j = 0; j < TS; j++) mx_new = fmaxf(mx_new, s[j]);
        float corr = __expf(mx - mx_new);
        l *= corr;
        #pragma unroll
        for (int j = 0; j < TS; j++) {
            float p = __expf(s[j] - mx_new);
            s[j] = p;
            l += p;
        }
        #pragma unroll
        for (int d = 0; d < AD; d++) o[d] *= corr;
        mx = mx_new;

        // o += p @ V
        #pragma unroll
        for (int j = 0; j < TS; j++) {
            const float4* v4 = (const float4*)Vs[j];
            float p = s[j];
            #pragma unroll
            for (int d = 0; d < 16; d++) {
                float4 vv = v4[d];
                o[4*d+0] += p * vv.x;
                o[4*d+1] += p * vv.y;
                o[4*d+2] += p * vv.z;
                o[4*d+3] += p * vv.w;
            }
        }
    }

    // write normalized output into [B,S,HID] layout for the final GEMM
    float inv = 1.f / l;
    float* op = g_o + ((size_t)(b * SSZ + q)) * HID + h * AD;
    #pragma unroll
    for (int i = 0; i < 16; i++) {
        float4 t;
        t.x = o[4*i+0] * inv; t.y = o[4*i+1] * inv;
        t.z = o[4*i+2] * inv; t.w = o[4*i+3] * inv;
        *(float4*)(op + 4 * i) = t;
    }
}

// ============================================================
// Kernel 3: output projection.  out[m,n] = sum_k g_o[m,k] * Wo[n,k]
// M=8192, N=1024, K=1024. Same tiling as kernel 1, plain epilogue.
// ============================================================
__global__ void __launch_bounds__(256) gemm_out_kernel(
    const float* __restrict__ W, float* __restrict__ C)
{
    __shared__ float As[16][128];
    __shared__ float Ws[16][128];

    const int bm = blockIdx.y * 128;
    const int bn = blockIdx.x * 128;
    const int tid = threadIdx.x;
    const int tx = tid & 15;
    const int ty = tid >> 4;

    float acc[8][8];
    #pragma unroll
    for (int i = 0; i < 8; i++)
        #pragma unroll
        for (int j = 0; j < 8; j++) acc[i][j] = 0.f;

    for (int k0 = 0; k0 < HID; k0 += 16) {
        #pragma unroll
        for (int it = 0; it < 2; it++) {
            int lin = tid + it * 256;
            int row = lin >> 2;
            int kq  = (lin & 3) << 2;
            float4 a = *(const float4*)(g_o + (size_t)(bm + row) * HID + k0 + kq);
            As[kq + 0][row] = a.x; As[kq + 1][row] = a.y;
            As[kq + 2][row] = a.z; As[kq + 3][row] = a.w;
            float4 w = *(const float4*)(W + (size_t)(bn + row) * HID + k0 + kq);
            Ws[kq + 0][row] = w.x; Ws[kq + 1][row] = w.y;
            Ws[kq + 2][row] = w.z; Ws[kq + 3][row] = w.w;
        }
        __syncthreads();
        #pragma unroll
        for (int k = 0; k < 16; k++) {
            float ar[8], br[8];
            *(float4*)(ar)     = *(const float4*)&As[k][ty * 8];
            *(float4*)(ar + 4) = *(const float4*)&As[k][ty * 8 + 4];
            *(float4*)(br)     = *(const float4*)&Ws[k][tx * 8];
            *(float4*)(br + 4) = *(const float4*)&Ws[k][tx * 8 + 4];
            #pragma unroll
            for (int i = 0; i < 8; i++)
                #pragma unroll
                for (int j = 0; j < 8; j++)
                    acc[i][j] += ar[i] * br[j];
        }
        __syncthreads();
    }

    const int n0 = bn + tx * 8;
    #pragma unroll
    for (int i = 0; i < 8; i++) {
        int m = bm + ty * 8 + i;
        float* dst = C + (size_t)m * HID + n0;
        *(float4*)(dst)     = *(const float4*)&acc[i][0];
        *(float4*)(dst + 4) = *(const float4*)&acc[i][4];
    }
}

// ============================================================
extern "C" void kernel_launch(void* const* d_in, const int* in_sizes, int n_in,
                              void* d_out, int out_size)
{
    const float*        iQ   = (const float*)d_in[0];
    const unsigned int* mask = (const unsigned int*)d_in[1];
    const float*        Wa   = (const float*)d_in[2];
    const float*        Wo   = (const float*)d_in[3];
    float*              out  = (float*)d_out;

    // 1) QKV projection: M=8192, N=3072
    {
        dim3 grid(3 * HID / 128, (BSZ * SSZ) / 128);   // (24, 64)
        gemm_qkv_kernel<<<grid, 256>>>(iQ, Wa);
    }
    // 2) attention
    {
        dim3 grid(SSZ / 128, BSZ * HN);                // (16, 64)
        attn_kernel<<<grid, 128>>>(mask);
    }
    // 3) output projection: M=8192, N=1024
    {
        dim3 grid(HID / 128, (BSZ * SSZ) / 128);       // (8, 64)
        gemm_out_kernel<<<grid, 256>>>(Wo, out);
    }
}

// round 4
// speedup vs baseline: 1.3188x; 1.3188x over previous
#include <cuda_runtime.h>
#include <cuda_bf16.h>
#include <cstdint>

// Problem dims (fixed by reference)
#define BSZ 4
#define SSZ 2048
#define DSZ 1024
#define HN  16
#define AD  64
#define HID 1024   // HN*AD
#define KTOT 1024

// ---------------- scratch (no allocs allowed) ----------------
__device__ float g_q[(size_t)BSZ * HN * SSZ * AD];   // [B,H,S,AD]
__device__ float g_k[(size_t)BSZ * HN * SSZ * AD];
__device__ float g_v[(size_t)BSZ * HN * SSZ * AD];
__device__ float g_o[(size_t)BSZ * SSZ * HID];       // [B,S,HID]

// bf16 split buffers
__device__ __nv_bfloat16 g_iQhi[(size_t)BSZ * SSZ * DSZ];
__device__ __nv_bfloat16 g_iQlo[(size_t)BSZ * SSZ * DSZ];
__device__ __nv_bfloat16 g_Wahi[(size_t)3 * HID * DSZ];
__device__ __nv_bfloat16 g_Walo[(size_t)3 * HID * DSZ];
__device__ __nv_bfloat16 g_ohi[(size_t)BSZ * SSZ * HID];
__device__ __nv_bfloat16 g_olo[(size_t)BSZ * SSZ * HID];
__device__ __nv_bfloat16 g_Wohi[(size_t)HID * HID];
__device__ __nv_bfloat16 g_Wolo[(size_t)HID * HID];

// ---------------- PTX helpers ----------------
__device__ __forceinline__ uint32_t smem_u32(const void* p) {
    uint32_t a;
    asm("{ .reg .u64 t; cvta.to.shared.u64 t, %1; cvt.u32.u64 %0, t; }" : "=r"(a) : "l"(p));
    return a;
}
#define CP_ASYNC16(dst, src) \
    asm volatile("cp.async.cg.shared.global [%0], [%1], 16;" :: "r"(dst), "l"(src) : "memory")
#define CP_COMMIT() asm volatile("cp.async.commit_group;" ::: "memory")
#define CP_WAIT1()  asm volatile("cp.async.wait_group 1;" ::: "memory")

#define LDSM_X4(r, addr) \
    asm volatile("ldmatrix.sync.aligned.m8n8.x4.shared.b16 {%0,%1,%2,%3}, [%4];" \
        : "=r"((r)[0]), "=r"((r)[1]), "=r"((r)[2]), "=r"((r)[3]) : "r"(addr))

#define MMA16816(c, a, b0, b1) \
    asm volatile("mma.sync.aligned.m16n8k16.row.col.f32.bf16.bf16.f32 " \
        "{%0,%1,%2,%3}, {%4,%5,%6,%7}, {%8,%9}, {%0,%1,%2,%3};" \
        : "+f"((c)[0]), "+f"((c)[1]), "+f"((c)[2]), "+f"((c)[3]) \
        : "r"((a)[0]), "r"((a)[1]), "r"((a)[2]), "r"((a)[3]), "r"(b0), "r"(b1))

// ============================================================
// fp32 -> (bf16 hi, bf16 lo) split.  One thread = 4 elements.
// ============================================================
__global__ void __launch_bounds__(256) split_kernel(
    const float* __restrict__ src, __nv_bfloat16* __restrict__ hi,
    __nv_bfloat16* __restrict__ lo)
{
    size_t i = (size_t)blockIdx.x * 256 + threadIdx.x;
    float4 x = ((const float4*)src)[i];
    __align__(8) __nv_bfloat16 h[4], l[4];
    float xs[4] = {x.x, x.y, x.z, x.w};
    #pragma unroll
    for (int j = 0; j < 4; j++) {
        h[j] = __float2bfloat16(xs[j]);
        l[j] = __float2bfloat16(xs[j] - __bfloat162float(h[j]));
    }
    *(uint2*)(hi + 4 * i) = *(uint2*)h;
    *(uint2*)(lo + 4 * i) = *(uint2*)l;
}

// ============================================================
// mma.sync bf16-split GEMM: C[m,n] = sum_k A[m,k]*B[n,k]  (both K-major)
// Block 128x128, 8 warps (warp tile 32x64), BK=32, 2-stage cp.async.
// 3 passes per k-step: Ah*Bh + Al*Bh + Ah*Bl (Al*Bl dropped, ~2^-16).
// Smem rows padded to 80B -> conflict-free ldmatrix.
// mode 0: scatter into g_q/g_k/g_v.  mode 1: plain store to Cplain.
// ============================================================
#define TSTRB  80                    // bytes per smem row (32 bf16 + 8 pad)
#define TILEB  (128 * TSTRB)         // 10240 B per tile
#define STAGEB (4 * TILEB)           // Ah, Al, Bh, Bl
#define GEMM_SMEM (2 * STAGEB)       // 81920 B

__global__ void __launch_bounds__(256) gemm_mma_kernel(
    const __nv_bfloat16* __restrict__ Ahi, const __nv_bfloat16* __restrict__ Alo,
    const __nv_bfloat16* __restrict__ Bhi, const __nv_bfloat16* __restrict__ Blo,
    float* __restrict__ Cplain, int mode)
{
    extern __shared__ char smem[];
    const uint32_t sb = smem_u32(smem);
    const int tid  = threadIdx.x;
    const int lane = tid & 31;
    const int wid  = tid >> 5;
    const int wm   = wid & 3;        // 4 m-tiles of 32
    const int wn   = wid >> 2;       // 2 n-tiles of 64
    const int bm = blockIdx.y * 128;
    const int bn = blockIdx.x * 128;

    const __nv_bfloat16* tsrc[4] = {Ahi, Alo, Bhi, Blo};

    // cp.async fill of one stage: 4 tiles x 512 16B-units
    auto load_stage = [&](int ch, int st) {
        #pragma unroll
        for (int t = 0; t < 4; t++) {
            const __nv_bfloat16* src = tsrc[t];
            const int rowbase = (t < 2) ? bm : bn;
            const uint32_t tb = sb + st * STAGEB + t * TILEB;
            #pragma unroll
            for (int i = 0; i < 2; i++) {
                int unit = tid + i * 256;          // 0..511
                int row = unit >> 2;
                int c16 = unit & 3;
                CP_ASYNC16(tb + row * TSTRB + c16 * 16,
                           src + (size_t)(rowbase + row) * KTOT + ch * 32 + c16 * 8);
            }
        }
    };

    float c[2][8][4];
    #pragma unroll
    for (int mi = 0; mi < 2; mi++)
        #pragma unroll
        for (int ni = 0; ni < 8; ni++)
            #pragma unroll
            for (int j = 0; j < 4; j++) c[mi][ni][j] = 0.f;

    // lane-dependent ldmatrix offsets (bytes)
    const uint32_t a_lane = (lane & 15) * TSTRB + (lane >> 4) * 16;
    const uint32_t b_lane = ((lane & 7) + ((lane >> 4) & 1) * 8) * TSTRB
                          + ((lane >> 3) & 1) * 16;

    load_stage(0, 0);
    CP_COMMIT();

    const int NCH = KTOT / 32;   // 32 chunks
    for (int ch = 0; ch < NCH; ch++) {
        const int st = ch & 1;
        if (ch + 1 < NCH) load_stage(ch + 1, st ^ 1);
        CP_COMMIT();
        CP_WAIT1();
        __syncthreads();

        const uint32_t sA  = sb + st * STAGEB;
        const uint32_t sAl = sA + TILEB;
        const uint32_t sBh = sA + 2 * TILEB;
        const uint32_t sBl = sA + 3 * TILEB;

        #pragma unroll
        for (int ks = 0; ks < 2; ks++) {
            const uint32_t ak = ks * 32;   // 16 bf16 = 32B per k-step
            uint32_t ah[2][4], al[2][4], bh[4][4], bl[4][4];
            #pragma unroll
            for (int mi = 0; mi < 2; mi++) {
                uint32_t ro = (wm * 32 + mi * 16) * TSTRB + a_lane + ak;
                LDSM_X4(ah[mi], sA + ro);
                LDSM_X4(al[mi], sAl + ro);
            }
            #pragma unroll
            for (int p = 0; p < 4; p++) {   // 4 n16-groups => 8 n8-frags
                uint32_t ro = (wn * 64 + p * 16) * TSTRB + b_lane + ak;
                LDSM_X4(bh[p], sBh + ro);
                LDSM_X4(bl[p], sBl + ro);
            }
            #pragma unroll
            for (int mi = 0; mi < 2; mi++)
                #pragma unroll
                for (int p = 0; p < 4; p++) {
                    MMA16816(c[mi][2*p],   ah[mi], bh[p][0], bh[p][1]);
                    MMA16816(c[mi][2*p+1], ah[mi], bh[p][2], bh[p][3]);
                    MMA16816(c[mi][2*p],   al[mi], bh[p][0], bh[p][1]);
                    MMA16816(c[mi][2*p+1], al[mi], bh[p][2], bh[p][3]);
                    MMA16816(c[mi][2*p],   ah[mi], bl[p][0], bl[p][1]);
                    MMA16816(c[mi][2*p+1], ah[mi], bl[p][2], bl[p][3]);
                }
        }
        __syncthreads();
    }

    // epilogue
    #pragma unroll
    for (int mi = 0; mi < 2; mi++) {
        const int r0 = bm + wm * 32 + mi * 16 + (lane >> 2);
        #pragma unroll
        for (int ni = 0; ni < 8; ni++) {
            const int ng = bn + wn * 64 + ni * 8 + (lane & 3) * 2;
            if (mode == 1) {
                float* d0 = Cplain + (size_t)r0 * HID + ng;
                float* d1 = Cplain + (size_t)(r0 + 8) * HID + ng;
                *(float2*)d0 = make_float2(c[mi][ni][0], c[mi][ni][1]);
                *(float2*)d1 = make_float2(c[mi][ni][2], c[mi][ni][3]);
            } else {
                const int which = ng >> 10;
                const int rr = ng & 1023;
                const int h  = rr >> 6;
                const int dd = rr & 63;
                float* tgt = (which == 0) ? g_q : ((which == 1) ? g_k : g_v);
                const int b0 = r0 >> 11, s0 = r0 & 2047;
                const int r1 = r0 + 8;
                const int b1 = r1 >> 11, s1 = r1 & 2047;
                float* d0 = tgt + (((size_t)(b0 * HN + h) * SSZ + s0) * AD + dd);
                float* d1 = tgt + (((size_t)(b1 * HN + h) * SSZ + s1) * AD + dd);
                *(float2*)d0 = make_float2(c[mi][ni][0], c[mi][ni][1]);
                *(float2*)d1 = make_float2(c[mi][ni][2], c[mi][ni][3]);
            }
        }
    }
}

// ============================================================
// Masked flash attention (fp32, unchanged from passing R2).
// ============================================================
#define TS 32

__global__ void __launch_bounds__(128) attn_kernel(const unsigned int* __restrict__ mask)
{
    __shared__ float Ks[TS][AD];
    __shared__ float Vs[TS][AD];

    const int bh = blockIdx.y;
    const int b  = bh >> 4;
    const int h  = bh & 15;
    const int q  = blockIdx.x * 128 + threadIdx.x;

    const float* qp    = g_q + ((size_t)bh * SSZ + q) * AD;
    const float* kbase = g_k + (size_t)bh * SSZ * AD;
    const float* vbase = g_v + (size_t)bh * SSZ * AD;
    const unsigned int* mrow = mask + ((size_t)b * SSZ + q) * SSZ;

    float qf[AD];
    {
        const float4* q4 = (const float4*)qp;
        #pragma unroll
        for (int i = 0; i < 16; i++) {
            float4 t = q4[i];
            qf[4*i+0] = t.x * 0.125f; qf[4*i+1] = t.y * 0.125f;
            qf[4*i+2] = t.z * 0.125f; qf[4*i+3] = t.w * 0.125f;
        }
    }

    float o[AD];
    #pragma unroll
    for (int d = 0; d < AD; d++) o[d] = 0.f;
    float mx = -1e30f, l = 0.f;

    for (int t0 = 0; t0 < SSZ; t0 += TS) {
        __syncthreads();
        #pragma unroll
        for (int it = 0; it < 4; it++) {
            int lin = threadIdx.x + it * 128;
            int rr = lin >> 4;
            int c4 = (lin & 15) << 2;
            *(float4*)&Ks[rr][c4] = *(const float4*)&kbase[(size_t)(t0 + rr) * AD + c4];
            *(float4*)&Vs[rr][c4] = *(const float4*)&vbase[(size_t)(t0 + rr) * AD + c4];
        }
        __syncthreads();

        unsigned int marr[TS];
        #pragma unroll
        for (int i = 0; i < 8; i++)
            *(uint4*)&marr[4 * i] = *(const uint4*)(mrow + t0 + 4 * i);

        float s[TS];
        #pragma unroll
        for (int j = 0; j < TS; j++) {
            const float4* k4 = (const float4*)Ks[j];
            float a0 = 0.f, a1 = 0.f, a2 = 0.f, a3 = 0.f;
            #pragma unroll
            for (int d = 0; d < 16; d++) {
                float4 kv = k4[d];
                a0 += qf[4*d+0] * kv.x;
                a1 += qf[4*d+1] * kv.y;
                a2 += qf[4*d+2] * kv.z;
                a3 += qf[4*d+3] * kv.w;
            }
            float sj = (a0 + a1) + (a2 + a3);
            s[j] = marr[j] ? -1e30f : sj;
        }

        float mx_new = mx;
        #pragma unroll
        for (int j = 0; j < TS; j++) mx_new = fmaxf(mx_new, s[j]);
        float corr = __expf(mx - mx_new);
        l *= corr;
        #pragma unroll
        for (int j = 0; j < TS; j++) {
            float p = __expf(s[j] - mx_new);
            s[j] = p;
            l += p;
        }
        #pragma unroll
        for (int d = 0; d < AD; d++) o[d] *= corr;
        mx = mx_new;

        #pragma unroll
        for (int j = 0; j < TS; j++) {
            const float4* v4 = (const float4*)Vs[j];
            float p = s[j];
            #pragma unroll
            for (int d = 0; d < 16; d++) {
                float4 vv = v4[d];
                o[4*d+0] += p * vv.x;
                o[4*d+1] += p * vv.y;
                o[4*d+2] += p * vv.z;
                o[4*d+3] += p * vv.w;
            }
        }
    }

    float inv = 1.f / l;
    float* op = g_o + ((size_t)(b * SSZ + q)) * HID + h * AD;
    #pragma unroll
    for (int i = 0; i < 16; i++) {
        float4 t;
        t.x = o[4*i+0] * inv; t.y = o[4*i+1] * inv;
        t.z = o[4*i+2] * inv; t.w = o[4*i+3] * inv;
        *(float4*)(op + 4 * i) = t;
    }
}

// ============================================================
extern "C" void kernel_launch(void* const* d_in, const int* in_sizes, int n_in,
                              void* d_out, int out_size)
{
    const float*        iQ   = (const float*)d_in[0];
    const unsigned int* mask = (const unsigned int*)d_in[1];
    const float*        Wa   = (const float*)d_in[2];
    const float*        Wo   = (const float*)d_in[3];
    float*              out  = (float*)d_out;

    cudaFuncSetAttribute(gemm_mma_kernel,
                         cudaFuncAttributeMaxDynamicSharedMemorySize, GEMM_SMEM);

    __nv_bfloat16 *iQhi, *iQlo, *Wahi, *Walo, *ohi, *olo, *Wohi, *Wolo;
    float *of;
    cudaGetSymbolAddress((void**)&iQhi, g_iQhi);
    cudaGetSymbolAddress((void**)&iQlo, g_iQlo);
    cudaGetSymbolAddress((void**)&Wahi, g_Wahi);
    cudaGetSymbolAddress((void**)&Walo, g_Walo);
    cudaGetSymbolAddress((void**)&ohi, g_ohi);
    cudaGetSymbolAddress((void**)&olo, g_olo);
    cudaGetSymbolAddress((void**)&Wohi, g_Wohi);
    cudaGetSymbolAddress((void**)&Wolo, g_Wolo);
    cudaGetSymbolAddress((void**)&of, g_o);

    // splits of iQ and Wa
    split_kernel<<<(BSZ * SSZ * DSZ) / 1024, 256>>>(iQ, iQhi, iQlo);
    split_kernel<<<(3 * HID * DSZ) / 1024, 256>>>(Wa, Wahi, Walo);

    // 1) QKV projection (tensor cores): M=8192, N=3072
    {
        dim3 grid(3 * HID / 128, (BSZ * SSZ) / 128);   // (24, 64)
        gemm_mma_kernel<<<grid, 256, GEMM_SMEM>>>(iQhi, iQlo, Wahi, Walo, nullptr, 0);
    }
    // 2) attention (fp32)
    {
        dim3 grid(SSZ / 128, BSZ * HN);                // (16, 64)
        attn_kernel<<<grid, 128>>>(mask);
    }
    // splits of attention output and Wo
    split_kernel<<<(BSZ * SSZ * HID) / 1024, 256>>>(of, ohi, olo);
    split_kernel<<<(HID * HID) / 1024, 256>>>(Wo, Wohi, Wolo);

    // 3) output projection (tensor cores): M=8192, N=1024
    {
        dim3 grid(HID / 128, (BSZ * SSZ) / 128);       // (8, 64)
        gemm_mma_kernel<<<grid, 256, GEMM_SMEM>>>(ohi, olo, Wohi, Wolo, out, 1);
    }
}

// round 5
// speedup vs baseline: 2.8817x; 2.1851x over previous
#include <cuda_runtime.h>
#include <cuda_bf16.h>
#include <cstdint>

// Problem dims (fixed by reference)
#define BSZ 4
#define SSZ 2048
#define DSZ 1024
#define HN  16
#define AD  64
#define HID 1024
#define KTOT 1024

// ---------------- scratch (no allocs allowed) ----------------
// bf16 split buffers
__device__ __nv_bfloat16 g_iQhi[(size_t)BSZ * SSZ * DSZ];
__device__ __nv_bfloat16 g_iQlo[(size_t)BSZ * SSZ * DSZ];
__device__ __nv_bfloat16 g_Wahi[(size_t)3 * HID * DSZ];
__device__ __nv_bfloat16 g_Walo[(size_t)3 * HID * DSZ];
__device__ __nv_bfloat16 g_Wohi[(size_t)HID * HID];
__device__ __nv_bfloat16 g_Wolo[(size_t)HID * HID];
// head-major Q/K/V hi/lo  [B,H,S,AD]
__device__ __nv_bfloat16 g_qh[(size_t)BSZ * HN * SSZ * AD];
__device__ __nv_bfloat16 g_ql[(size_t)BSZ * HN * SSZ * AD];
__device__ __nv_bfloat16 g_kh[(size_t)BSZ * HN * SSZ * AD];
__device__ __nv_bfloat16 g_kl[(size_t)BSZ * HN * SSZ * AD];
__device__ __nv_bfloat16 g_vh[(size_t)BSZ * HN * SSZ * AD];
__device__ __nv_bfloat16 g_vl[(size_t)BSZ * HN * SSZ * AD];
// attention output hi/lo  [B,S,HID]
__device__ __nv_bfloat16 g_oh[(size_t)BSZ * SSZ * HID];
__device__ __nv_bfloat16 g_ol[(size_t)BSZ * SSZ * HID];

// ---------------- PTX helpers ----------------
__device__ __forceinline__ uint32_t smem_u32(const void* p) {
    uint32_t a;
    asm("{ .reg .u64 t; cvta.to.shared.u64 t, %1; cvt.u32.u64 %0, t; }" : "=r"(a) : "l"(p));
    return a;
}
#define CP_ASYNC16(dst, src) \
    asm volatile("cp.async.cg.shared.global [%0], [%1], 16;" :: "r"(dst), "l"(src) : "memory")
#define CP_COMMIT() asm volatile("cp.async.commit_group;" ::: "memory")
#define CP_WAIT1()  asm volatile("cp.async.wait_group 1;" ::: "memory")
#define CP_WAIT0()  asm volatile("cp.async.wait_group 0;" ::: "memory")

#define LDSM_X4(r, addr) \
    asm volatile("ldmatrix.sync.aligned.m8n8.x4.shared.b16 {%0,%1,%2,%3}, [%4];" \
        : "=r"((r)[0]), "=r"((r)[1]), "=r"((r)[2]), "=r"((r)[3]) : "r"(addr))
#define LDSM_X4_T(r, addr) \
    asm volatile("ldmatrix.sync.aligned.m8n8.x4.trans.shared.b16 {%0,%1,%2,%3}, [%4];" \
        : "=r"((r)[0]), "=r"((r)[1]), "=r"((r)[2]), "=r"((r)[3]) : "r"(addr))

#define MMA16816(c, a, b0, b1) \
    asm volatile("mma.sync.aligned.m16n8k16.row.col.f32.bf16.bf16.f32 " \
        "{%0,%1,%2,%3}, {%4,%5,%6,%7}, {%8,%9}, {%0,%1,%2,%3};" \
        : "+f"((c)[0]), "+f"((c)[1]), "+f"((c)[2]), "+f"((c)[3]) \
        : "r"((a)[0]), "r"((a)[1]), "r"((a)[2]), "r"((a)[3]), "r"(b0), "r"(b1))

// pack two floats into bf16x2 (flo -> low half, fhi -> high half)
#define PACK_BF2(u, flo, fhi) \
    asm("cvt.rn.bf16x2.f32 %0, %1, %2;" : "=r"(u) : "f"(fhi), "f"(flo))

// ============================================================
// fp32 -> (bf16 hi, bf16 lo) split.  One thread = 4 elements.
// ============================================================
__global__ void __launch_bounds__(256) split_kernel(
    const float* __restrict__ src, __nv_bfloat16* __restrict__ hi,
    __nv_bfloat16* __restrict__ lo)
{
    size_t i = (size_t)blockIdx.x * 256 + threadIdx.x;
    float4 x = ((const float4*)src)[i];
    __align__(8) __nv_bfloat16 h[4], l[4];
    float xs[4] = {x.x, x.y, x.z, x.w};
    #pragma unroll
    for (int j = 0; j < 4; j++) {
        h[j] = __float2bfloat16(xs[j]);
        l[j] = __float2bfloat16(xs[j] - __bfloat162float(h[j]));
    }
    *(uint2*)(hi + 4 * i) = *(uint2*)h;
    *(uint2*)(lo + 4 * i) = *(uint2*)l;
}

// ============================================================
// mma.sync bf16-split GEMM: C[m,n] = sum_k A[m,k]*B[n,k]  (both K-major)
// Block 128x128, 8 warps (warp tile 32x64), BK=32, 2-stage cp.async.
// mode 0: epilogue splits to bf16 hi/lo into g_q/k/v (Q scaled by 0.125).
// mode 1: plain fp32 store to Cplain.
// ============================================================
#define TSTRB  80
#define TILEB  (128 * TSTRB)
#define STAGEB (4 * TILEB)
#define GEMM_SMEM (2 * STAGEB)

__global__ void __launch_bounds__(256) gemm_mma_kernel(
    const __nv_bfloat16* __restrict__ Ahi, const __nv_bfloat16* __restrict__ Alo,
    const __nv_bfloat16* __restrict__ Bhi, const __nv_bfloat16* __restrict__ Blo,
    float* __restrict__ Cplain, int mode)
{
    extern __shared__ char smem[];
    const uint32_t sb = smem_u32(smem);
    const int tid  = threadIdx.x;
    const int lane = tid & 31;
    const int wid  = tid >> 5;
    const int wm   = wid & 3;
    const int wn   = wid >> 2;
    const int bm = blockIdx.y * 128;
    const int bn = blockIdx.x * 128;

    const __nv_bfloat16* tsrc[4] = {Ahi, Alo, Bhi, Blo};

    auto load_stage = [&](int ch, int st) {
        #pragma unroll
        for (int t = 0; t < 4; t++) {
            const __nv_bfloat16* src = tsrc[t];
            const int rowbase = (t < 2) ? bm : bn;
            const uint32_t tb = sb + st * STAGEB + t * TILEB;
            #pragma unroll
            for (int i = 0; i < 2; i++) {
                int unit = tid + i * 256;
                int row = unit >> 2;
                int c16 = unit & 3;
                CP_ASYNC16(tb + row * TSTRB + c16 * 16,
                           src + (size_t)(rowbase + row) * KTOT + ch * 32 + c16 * 8);
            }
        }
    };

    float c[2][8][4];
    #pragma unroll
    for (int mi = 0; mi < 2; mi++)
        #pragma unroll
        for (int ni = 0; ni < 8; ni++)
            #pragma unroll
            for (int j = 0; j < 4; j++) c[mi][ni][j] = 0.f;

    const uint32_t a_lane = (lane & 15) * TSTRB + (lane >> 4) * 16;
    const uint32_t b_lane = ((lane & 7) + ((lane >> 4) & 1) * 8) * TSTRB
                          + ((lane >> 3) & 1) * 16;

    load_stage(0, 0);
    CP_COMMIT();

    const int NCH = KTOT / 32;
    for (int ch = 0; ch < NCH; ch++) {
        const int st = ch & 1;
        if (ch + 1 < NCH) load_stage(ch + 1, st ^ 1);
        CP_COMMIT();
        CP_WAIT1();
        __syncthreads();

        const uint32_t sA  = sb + st * STAGEB;
        const uint32_t sAl = sA + TILEB;
        const uint32_t sBh = sA + 2 * TILEB;
        const uint32_t sBl = sA + 3 * TILEB;

        #pragma unroll
        for (int ks = 0; ks < 2; ks++) {
            const uint32_t ak = ks * 32;
            uint32_t ah[2][4], al[2][4], bh[4][4], bl[4][4];
            #pragma unroll
            for (int mi = 0; mi < 2; mi++) {
                uint32_t ro = (wm * 32 + mi * 16) * TSTRB + a_lane + ak;
                LDSM_X4(ah[mi], sA + ro);
                LDSM_X4(al[mi], sAl + ro);
            }
            #pragma unroll
            for (int p = 0; p < 4; p++) {
                uint32_t ro = (wn * 64 + p * 16) * TSTRB + b_lane + ak;
                LDSM_X4(bh[p], sBh + ro);
                LDSM_X4(bl[p], sBl + ro);
            }
            #pragma unroll
            for (int mi = 0; mi < 2; mi++)
                #pragma unroll
                for (int p = 0; p < 4; p++) {
                    MMA16816(c[mi][2*p],   ah[mi], bh[p][0], bh[p][1]);
                    MMA16816(c[mi][2*p+1], ah[mi], bh[p][2], bh[p][3]);
                    MMA16816(c[mi][2*p],   al[mi], bh[p][0], bh[p][1]);
                    MMA16816(c[mi][2*p+1], al[mi], bh[p][2], bh[p][3]);
                    MMA16816(c[mi][2*p],   ah[mi], bl[p][0], bl[p][1]);
                    MMA16816(c[mi][2*p+1], ah[mi], bl[p][2], bl[p][3]);
                }
        }
        __syncthreads();
    }

    // epilogue
    #pragma unroll
    for (int mi = 0; mi < 2; mi++) {
        const int r0 = bm + wm * 32 + mi * 16 + (lane >> 2);
        #pragma unroll
        for (int ni = 0; ni < 8; ni++) {
            const int ng = bn + wn * 64 + ni * 8 + (lane & 3) * 2;
            if (mode == 1) {
                float* d0 = Cplain + (size_t)r0 * HID + ng;
                float* d1 = Cplain + (size_t)(r0 + 8) * HID + ng;
                *(float2*)d0 = make_float2(c[mi][ni][0], c[mi][ni][1]);
                *(float2*)d1 = make_float2(c[mi][ni][2], c[mi][ni][3]);
            } else {
                const int which = ng >> 10;
                const int rr = ng & 1023;
                const int hh = rr >> 6;
                const int dd = rr & 63;
                const float sc = (which == 0) ? 0.125f : 1.f;
                __nv_bfloat16 *dsth, *dstl;
                if (which == 0)      { dsth = g_qh; dstl = g_ql; }
                else if (which == 1) { dsth = g_kh; dstl = g_kl; }
                else                 { dsth = g_vh; dstl = g_vl; }
                #pragma unroll
                for (int half = 0; half < 2; half++) {
                    const int r = r0 + half * 8;
                    const int b = r >> 11, s = r & 2047;
                    size_t e = (((size_t)(b * HN + hh) * SSZ + s)) * AD + dd;
                    float v0 = c[mi][ni][half * 2 + 0] * sc;
                    float v1 = c[mi][ni][half * 2 + 1] * sc;
                    uint32_t uh;
                    PACK_BF2(uh, v0, v1);
                    float h0 = __uint_as_float(uh << 16);
                    float h1 = __uint_as_float(uh & 0xffff0000u);
                    uint32_t ul;
                    PACK_BF2(ul, v0 - h0, v1 - h1);
                    *(uint32_t*)&dsth[e] = uh;
                    *(uint32_t*)&dstl[e] = ul;
                }
            }
        }
    }
}

// ============================================================
// Flash attention with mma.sync bf16-split.
// Block: 128 q-rows, 8 warps (16 rows each), KV tiles of 64, 2-stage cp.async.
// QK: Qh*Kh + Ql*Kh + Qh*Kl.  PV: Ph*Vh + Pl*Vh + Ph*Vl.
// ============================================================
#define ARS   144                 // smem row stride (128B data + 16 pad)
#define ATILE (64 * ARS)          // 9216
#define ASTG  (4 * ATILE)         // 36864: Khi, Klo, Vhi, Vlo
#define ATTN_SMEM (2 * ASTG)      // 73728

__global__ void __launch_bounds__(256) attn_mma_kernel(const int* __restrict__ mask)
{
    extern __shared__ char smem[];
    const uint32_t sb = smem_u32(smem);
    const int tid = threadIdx.x, lane = tid & 31, w = tid >> 5;
    const int bh = blockIdx.y, b = bh >> 4, h = bh & 15;
    const int bm = blockIdx.x * 128;

    const __nv_bfloat16* qh = g_qh + (size_t)bh * SSZ * AD;
    const __nv_bfloat16* ql = g_ql + (size_t)bh * SSZ * AD;
    const __nv_bfloat16* kh = g_kh + (size_t)bh * SSZ * AD;
    const __nv_bfloat16* kl = g_kl + (size_t)bh * SSZ * AD;
    const __nv_bfloat16* vh = g_vh + (size_t)bh * SSZ * AD;
    const __nv_bfloat16* vl = g_vl + (size_t)bh * SSZ * AD;

    // ---- load Q tile (hi at 0, lo at 2*ATILE=18432) into stage0 area ----
    #pragma unroll
    for (int i = 0; i < 8; i++) {
        int unit = tid + i * 256;          // 0..2047
        int half = unit >> 10;
        int rr   = (unit >> 3) & 127;
        int c16  = unit & 7;
        const __nv_bfloat16* src = half ? ql : qh;
        CP_ASYNC16(sb + half * 18432 + rr * ARS + c16 * 16,
                   src + (size_t)(bm + rr) * AD + c16 * 8);
    }
    CP_COMMIT();
    CP_WAIT0();
    __syncthreads();

    uint32_t aq[2][4][4];
    {
        const uint32_t a_lane = (lane & 15) * ARS + (lane >> 4) * 16;
        #pragma unroll
        for (int hf = 0; hf < 2; hf++)
            #pragma unroll
            for (int ks = 0; ks < 4; ks++)
                LDSM_X4(aq[hf][ks], sb + hf * 18432 + (w * 16) * ARS + a_lane + ks * 32);
    }
    __syncthreads();

    auto load_stage = [&](int t0, int st) {
        #pragma unroll
        for (int i = 0; i < 8; i++) {
            int unit = tid + i * 256;      // 0..2047
            int t    = unit >> 9;          // 0..3
            int rr   = (unit >> 3) & 63;
            int c16  = unit & 7;
            const __nv_bfloat16* src = (t == 0) ? kh : (t == 1) ? kl : (t == 2) ? vh : vl;
            CP_ASYNC16(sb + st * ASTG + t * ATILE + rr * ARS + c16 * 16,
                       src + (size_t)(t0 + rr) * AD + c16 * 8);
        }
    };

    float co[8][4];
    #pragma unroll
    for (int ni = 0; ni < 8; ni++)
        #pragma unroll
        for (int j = 0; j < 4; j++) co[ni][j] = 0.f;
    float mx0 = -1e30f, mx1 = -1e30f, l0 = 0.f, l1 = 0.f;

    const int qr = bm + w * 16 + (lane >> 2);
    const int* mrow0 = mask + ((size_t)b * SSZ + qr) * SSZ;
    const int* mrow1 = mrow0 + (size_t)8 * SSZ;
    const uint32_t b_lane = ((lane & 7) + ((lane >> 4) & 1) * 8) * ARS + ((lane >> 3) & 1) * 16;
    const uint32_t v_lane = ((lane & 7) + ((lane >> 3) & 1) * 8) * ARS + ((lane >> 4) & 1) * 16;

    load_stage(0, 0);
    CP_COMMIT();

    for (int t = 0; t < SSZ / 64; t++) {
        const int st = t & 1;
        if (t + 1 < SSZ / 64) load_stage((t + 1) * 64, st ^ 1);
        CP_COMMIT();
        CP_WAIT1();
        __syncthreads();

        const uint32_t sKh = sb + st * ASTG;
        const uint32_t sKl = sKh + ATILE;
        const uint32_t sVh = sKh + 2 * ATILE;
        const uint32_t sVl = sKh + 3 * ATILE;

        // ---- scores S = Q K^T (3 split passes) ----
        float s[8][4];
        #pragma unroll
        for (int ni = 0; ni < 8; ni++)
            #pragma unroll
            for (int j = 0; j < 4; j++) s[ni][j] = 0.f;

        #pragma unroll
        for (int ks = 0; ks < 4; ks++) {
            #pragma unroll
            for (int p = 0; p < 4; p++) {
                uint32_t kf[4], klf[4];
                LDSM_X4(kf,  sKh + (p * 16) * ARS + b_lane + ks * 32);
                LDSM_X4(klf, sKl + (p * 16) * ARS + b_lane + ks * 32);
                MMA16816(s[2*p],   aq[0][ks], kf[0], kf[1]);
                MMA16816(s[2*p+1], aq[0][ks], kf[2], kf[3]);
                MMA16816(s[2*p],   aq[1][ks], kf[0], kf[1]);
                MMA16816(s[2*p+1], aq[1][ks], kf[2], kf[3]);
                MMA16816(s[2*p],   aq[0][ks], klf[0], klf[1]);
                MMA16816(s[2*p+1], aq[0][ks], klf[2], klf[3]);
            }
        }

        // ---- mask ----
        const int kb = t * 64;
        #pragma unroll
        for (int ni = 0; ni < 8; ni++) {
            const int key = kb + ni * 8 + (lane & 3) * 2;
            int2 m0 = *(const int2*)(mrow0 + key);
            int2 m1 = *(const int2*)(mrow1 + key);
            if (m0.x) s[ni][0] = -1e30f;
            if (m0.y) s[ni][1] = -1e30f;
            if (m1.x) s[ni][2] = -1e30f;
            if (m1.y) s[ni][3] = -1e30f;
        }

        // ---- online softmax ----
        float tm0 = -1e30f, tm1 = -1e30f;
        #pragma unroll
        for (int ni = 0; ni < 8; ni++) {
            tm0 = fmaxf(tm0, fmaxf(s[ni][0], s[ni][1]));
            tm1 = fmaxf(tm1, fmaxf(s[ni][2], s[ni][3]));
        }
        tm0 = fmaxf(tm0, __shfl_xor_sync(0xffffffffu, tm0, 1));
        tm0 = fmaxf(tm0, __shfl_xor_sync(0xffffffffu, tm0, 2));
        tm1 = fmaxf(tm1, __shfl_xor_sync(0xffffffffu, tm1, 1));
        tm1 = fmaxf(tm1, __shfl_xor_sync(0xffffffffu, tm1, 2));
        const float mn0 = fmaxf(mx0, tm0), mn1 = fmaxf(mx1, tm1);
        const float cr0 = __expf(mx0 - mn0), cr1 = __expf(mx1 - mn1);
        l0 *= cr0; l1 *= cr1;
        mx0 = mn0; mx1 = mn1;
        #pragma unroll
        for (int ni = 0; ni < 8; ni++) {
            s[ni][0] = __expf(s[ni][0] - mn0);
            s[ni][1] = __expf(s[ni][1] - mn0);
            s[ni][2] = __expf(s[ni][2] - mn1);
            s[ni][3] = __expf(s[ni][3] - mn1);
            l0 += s[ni][0] + s[ni][1];
            l1 += s[ni][2] + s[ni][3];
            co[ni][0] *= cr0; co[ni][1] *= cr0;
            co[ni][2] *= cr1; co[ni][3] *= cr1;
        }

        // ---- O += P V (split P, split V) ----
        #pragma unroll
        for (int ks = 0; ks < 4; ks++) {
            uint32_t ph[4], pl[4];
            #pragma unroll
            for (int half = 0; half < 2; half++) {
                const int ni = 2 * ks + half;
                float f0 = s[ni][0], f1 = s[ni][1], f2 = s[ni][2], f3 = s[ni][3];
                uint32_t u01, u23;
                PACK_BF2(u01, f0, f1);
                PACK_BF2(u23, f2, f3);
                ph[half * 2]     = u01;
                ph[half * 2 + 1] = u23;
                float h0 = __uint_as_float(u01 << 16), h1 = __uint_as_float(u01 & 0xffff0000u);
                float h2 = __uint_as_float(u23 << 16), h3 = __uint_as_float(u23 & 0xffff0000u);
                PACK_BF2(pl[half * 2],     f0 - h0, f1 - h1);
                PACK_BF2(pl[half * 2 + 1], f2 - h2, f3 - h3);
            }
            #pragma unroll
            for (int p = 0; p < 4; p++) {
                uint32_t vf[4], vlf[4];
                LDSM_X4_T(vf,  sVh + (ks * 16) * ARS + p * 32 + v_lane);
                LDSM_X4_T(vlf, sVl + (ks * 16) * ARS + p * 32 + v_lane);
                MMA16816(co[2*p],   ph, vf[0], vf[1]);
                MMA16816(co[2*p+1], ph, vf[2], vf[3]);
                MMA16816(co[2*p],   pl, vf[0], vf[1]);
                MMA16816(co[2*p+1], pl, vf[2], vf[3]);
                MMA16816(co[2*p],   ph, vlf[0], vlf[1]);
                MMA16816(co[2*p+1], ph, vlf[2], vlf[3]);
            }
        }
        __syncthreads();
    }

    // ---- epilogue: normalize, split to bf16 hi/lo, write [B,S,HID] ----
    l0 += __shfl_xor_sync(0xffffffffu, l0, 1);
    l0 += __shfl_xor_sync(0xffffffffu, l0, 2);
    l1 += __shfl_xor_sync(0xffffffffu, l1, 1);
    l1 += __shfl_xor_sync(0xffffffffu, l1, 2);
    const float i0 = 1.f / l0, i1 = 1.f / l1;

    const size_t d0 = ((size_t)b * SSZ + qr) * HID + h * AD;
    const size_t d1 = ((size_t)b * SSZ + qr + 8) * HID + h * AD;
    #pragma unroll
    for (int ni = 0; ni < 8; ni++) {
        const int dd = ni * 8 + (lane & 3) * 2;
        float v0 = co[ni][0] * i0, v1 = co[ni][1] * i0;
        float v2 = co[ni][2] * i1, v3 = co[ni][3] * i1;
        uint32_t uh0, uh1, ul0, ul1;
        PACK_BF2(uh0, v0, v1);
        PACK_BF2(uh1, v2, v3);
        float a0 = __uint_as_float(uh0 << 16), a1 = __uint_as_float(uh0 & 0xffff0000u);
        float a2 = __uint_as_float(uh1 << 16), a3 = __uint_as_float(uh1 & 0xffff0000u);
        PACK_BF2(ul0, v0 - a0, v1 - a1);
        PACK_BF2(ul1, v2 - a2, v3 - a3);
        *(uint32_t*)&g_oh[d0 + dd] = uh0;
        *(uint32_t*)&g_ol[d0 + dd] = ul0;
        *(uint32_t*)&g_oh[d1 + dd] = uh1;
        *(uint32_t*)&g_ol[d1 + dd] = ul1;
    }
}

// ============================================================
extern "C" void kernel_launch(void* const* d_in, const int* in_sizes, int n_in,
                              void* d_out, int out_size)
{
    const float* iQ   = (const float*)d_in[0];
    const int*   mask = (const int*)d_in[1];
    const float* Wa   = (const float*)d_in[2];
    const float* Wo   = (const float*)d_in[3];
    float*       out  = (float*)d_out;

    cudaFuncSetAttribute(gemm_mma_kernel,
                         cudaFuncAttributeMaxDynamicSharedMemorySize, GEMM_SMEM);
    cudaFuncSetAttribute(attn_mma_kernel,
                         cudaFuncAttributeMaxDynamicSharedMemorySize, ATTN_SMEM);

    __nv_bfloat16 *iQhi, *iQlo, *Wahi, *Walo, *Wohi, *Wolo, *oh, *ol;
    cudaGetSymbolAddress((void**)&iQhi, g_iQhi);
    cudaGetSymbolAddress((void**)&iQlo, g_iQlo);
    cudaGetSymbolAddress((void**)&Wahi, g_Wahi);
    cudaGetSymbolAddress((void**)&Walo, g_Walo);
    cudaGetSymbolAddress((void**)&Wohi, g_Wohi);
    cudaGetSymbolAddress((void**)&Wolo, g_Wolo);
    cudaGetSymbolAddress((void**)&oh, g_oh);
    cudaGetSymbolAddress((void**)&ol, g_ol);

    // splits
    split_kernel<<<(BSZ * SSZ * DSZ) / 1024, 256>>>(iQ, iQhi, iQlo);
    split_kernel<<<(3 * HID * DSZ) / 1024, 256>>>(Wa, Wahi, Walo);
    split_kernel<<<(HID * HID) / 1024, 256>>>(Wo, Wohi, Wolo);

    // 1) QKV projection -> bf16 hi/lo head-major Q(scaled)/K/V
    {
        dim3 grid(3 * HID / 128, (BSZ * SSZ) / 128);   // (24, 64)
        gemm_mma_kernel<<<grid, 256, GEMM_SMEM>>>(iQhi, iQlo, Wahi, Walo, nullptr, 0);
    }
    // 2) attention (tensor cores) -> bf16 hi/lo O
    {
        dim3 grid(SSZ / 128, BSZ * HN);                // (16, 64)
        attn_mma_kernel<<<grid, 256, ATTN_SMEM>>>(mask);
    }
    // 3) output projection -> fp32 out
    {
        dim3 grid(HID / 128, (BSZ * SSZ) / 128);       // (8, 64)
        gemm_mma_kernel<<<grid, 256, GEMM_SMEM>>>(oh, ol, Wohi, Wolo, out, 1);
    }
}

// round 6
// speedup vs baseline: 6.2532x; 2.1700x over previous
#include <cuda_runtime.h>
#include <cuda_fp16.h>
#include <cstdint>

// Problem dims (fixed by reference)
#define BSZ 4
#define SSZ 2048
#define DSZ 1024
#define HN  16
#define AD  64
#define HID 1024
#define KTOT 1024

// ---------------- scratch (no allocs allowed) ----------------
__device__ __half g_iQ16[(size_t)BSZ * SSZ * DSZ];
__device__ __half g_Wa16[(size_t)3 * HID * DSZ];
__device__ __half g_Wo16[(size_t)HID * HID];
// head-major Q/K/V fp16  [B,H,S,AD]  (Q pre-scaled by 0.125)
__device__ __half g_q16[(size_t)BSZ * HN * SSZ * AD];
__device__ __half g_k16[(size_t)BSZ * HN * SSZ * AD];
__device__ __half g_v16[(size_t)BSZ * HN * SSZ * AD];
// attention output fp16  [B,S,HID]
__device__ __half g_o16[(size_t)BSZ * SSZ * HID];

// ---------------- PTX helpers ----------------
__device__ __forceinline__ uint32_t smem_u32(const void* p) {
    uint32_t a;
    asm("{ .reg .u64 t; cvta.to.shared.u64 t, %1; cvt.u32.u64 %0, t; }" : "=r"(a) : "l"(p));
    return a;
}
#define CP_ASYNC16(dst, src) \
    asm volatile("cp.async.cg.shared.global [%0], [%1], 16;" :: "r"(dst), "l"(src) : "memory")
#define CP_COMMIT() asm volatile("cp.async.commit_group;" ::: "memory")
#define CP_WAIT1()  asm volatile("cp.async.wait_group 1;" ::: "memory")
#define CP_WAIT0()  asm volatile("cp.async.wait_group 0;" ::: "memory")

#define LDSM_X4(r, addr) \
    asm volatile("ldmatrix.sync.aligned.m8n8.x4.shared.b16 {%0,%1,%2,%3}, [%4];" \
        : "=r"((r)[0]), "=r"((r)[1]), "=r"((r)[2]), "=r"((r)[3]) : "r"(addr))
#define LDSM_X4_T(r, addr) \
    asm volatile("ldmatrix.sync.aligned.m8n8.x4.trans.shared.b16 {%0,%1,%2,%3}, [%4];" \
        : "=r"((r)[0]), "=r"((r)[1]), "=r"((r)[2]), "=r"((r)[3]) : "r"(addr))

#define MMAF16(c, a, b0, b1) \
    asm volatile("mma.sync.aligned.m16n8k16.row.col.f32.f16.f16.f32 " \
        "{%0,%1,%2,%3}, {%4,%5,%6,%7}, {%8,%9}, {%0,%1,%2,%3};" \
        : "+f"((c)[0]), "+f"((c)[1]), "+f"((c)[2]), "+f"((c)[3]) \
        : "r"((a)[0]), "r"((a)[1]), "r"((a)[2]), "r"((a)[3]), "r"(b0), "r"(b1))

// pack two floats into f16x2 (flo -> low half, fhi -> high half)
#define PACK_F16X2(u, flo, fhi) \
    asm("cvt.rn.f16x2.f32 %0, %1, %2;" : "=r"(u) : "f"(fhi), "f"(flo))

// ============================================================
// fp32 -> fp16 convert.  One thread = 8 elements.
// ============================================================
__global__ void __launch_bounds__(256) cvt_kernel(
    const float* __restrict__ src, __half* __restrict__ dst)
{
    size_t i = (size_t)blockIdx.x * 256 + threadIdx.x;
    float4 x0 = ((const float4*)src)[2 * i];
    float4 x1 = ((const float4*)src)[2 * i + 1];
    uint4 o;
    PACK_F16X2(o.x, x0.x, x0.y);
    PACK_F16X2(o.y, x0.z, x0.w);
    PACK_F16X2(o.z, x1.x, x1.y);
    PACK_F16X2(o.w, x1.z, x1.w);
    ((uint4*)dst)[i] = o;
}

// ============================================================
// fp16 single-pass GEMM: C[m,n] = sum_k A[m,k]*B[n,k]  (both K-major)
// Block 128x128, 8 warps (warp 32x64), BK=64 (144B padded rows), 2-stage.
// mode 0: epilogue -> fp16 head-major g_q16(scaled)/g_k16/g_v16.
// mode 1: fp32 store to Cplain.
// ============================================================
#define GRS    144                  // row stride bytes (128B data + 16 pad)
#define GTILE  (128 * GRS)          // 18432
#define GSTAGE (2 * GTILE)          // A + B
#define GEMM_SMEM (2 * GSTAGE)      // 73728

__global__ void __launch_bounds__(256) gemm_f16_kernel(
    const __half* __restrict__ A, const __half* __restrict__ B,
    float* __restrict__ Cplain, int mode)
{
    extern __shared__ char smem[];
    const uint32_t sb = smem_u32(smem);
    const int tid  = threadIdx.x;
    const int lane = tid & 31;
    const int wid  = tid >> 5;
    const int wm   = wid & 3;
    const int wn   = wid >> 2;
    const int bm = blockIdx.y * 128;
    const int bn = blockIdx.x * 128;

    auto load_stage = [&](int ch, int st) {
        #pragma unroll
        for (int i = 0; i < 8; i++) {
            int unit = tid + i * 256;        // 0..2047
            int t    = unit >> 10;           // 0 = A, 1 = B
            int rr   = (unit >> 3) & 127;
            int c16  = unit & 7;
            const __half* src = t ? B : A;
            const int rowbase = t ? bn : bm;
            CP_ASYNC16(sb + st * GSTAGE + t * GTILE + rr * GRS + c16 * 16,
                       src + (size_t)(rowbase + rr) * KTOT + ch * 64 + c16 * 8);
        }
    };

    float c[2][8][4];
    #pragma unroll
    for (int mi = 0; mi < 2; mi++)
        #pragma unroll
        for (int ni = 0; ni < 8; ni++)
            #pragma unroll
            for (int j = 0; j < 4; j++) c[mi][ni][j] = 0.f;

    const uint32_t a_lane = (lane & 15) * GRS + (lane >> 4) * 16;
    const uint32_t b_lane = ((lane & 7) + ((lane >> 4) & 1) * 8) * GRS
                          + ((lane >> 3) & 1) * 16;

    load_stage(0, 0);
    CP_COMMIT();

    const int NCH = KTOT / 64;   // 16 chunks
    for (int ch = 0; ch < NCH; ch++) {
        const int st = ch & 1;
        if (ch + 1 < NCH) load_stage(ch + 1, st ^ 1);
        CP_COMMIT();
        CP_WAIT1();
        __syncthreads();

        const uint32_t sA = sb + st * GSTAGE;
        const uint32_t sB = sA + GTILE;

        #pragma unroll
        for (int ks = 0; ks < 4; ks++) {
            const uint32_t ak = ks * 32;    // 16 fp16 = 32B
            uint32_t af[2][4], bf[4][4];
            #pragma unroll
            for (int mi = 0; mi < 2; mi++)
                LDSM_X4(af[mi], sA + (wm * 32 + mi * 16) * GRS + a_lane + ak);
            #pragma unroll
            for (int p = 0; p < 4; p++)
                LDSM_X4(bf[p], sB + (wn * 64 + p * 16) * GRS + b_lane + ak);
            #pragma unroll
            for (int mi = 0; mi < 2; mi++)
                #pragma unroll
                for (int p = 0; p < 4; p++) {
                    MMAF16(c[mi][2*p],   af[mi], bf[p][0], bf[p][1]);
                    MMAF16(c[mi][2*p+1], af[mi], bf[p][2], bf[p][3]);
                }
        }
        __syncthreads();
    }

    // epilogue
    #pragma unroll
    for (int mi = 0; mi < 2; mi++) {
        const int r0 = bm + wm * 32 + mi * 16 + (lane >> 2);
        #pragma unroll
        for (int ni = 0; ni < 8; ni++) {
            const int ng = bn + wn * 64 + ni * 8 + (lane & 3) * 2;
            if (mode == 1) {
                float* d0 = Cplain + (size_t)r0 * HID + ng;
                float* d1 = Cplain + (size_t)(r0 + 8) * HID + ng;
                *(float2*)d0 = make_float2(c[mi][ni][0], c[mi][ni][1]);
                *(float2*)d1 = make_float2(c[mi][ni][2], c[mi][ni][3]);
            } else {
                const int which = ng >> 10;
                const int rr = ng & 1023;
                const int hh = rr >> 6;
                const int dd = rr & 63;
                const float sc = (which == 0) ? 0.125f : 1.f;
                __half* dst = (which == 0) ? g_q16 : ((which == 1) ? g_k16 : g_v16);
                #pragma unroll
                for (int half = 0; half < 2; half++) {
                    const int r = r0 + half * 8;
                    const int b = r >> 11, s = r & 2047;
                    size_t e = (((size_t)(b * HN + hh) * SSZ + s)) * AD + dd;
                    uint32_t u;
                    PACK_F16X2(u, c[mi][ni][half * 2] * sc, c[mi][ni][half * 2 + 1] * sc);
                    *(uint32_t*)&dst[e] = u;
                }
            }
        }
    }
}

// ============================================================
// Flash attention, single-pass fp16 mma.
// Block: 128 q-rows, 8 warps (16 rows each), KV tiles of 64, 2-stage.
// ============================================================
#define ARS   144
#define ATILE (64 * ARS)            // 9216
#define ASTG  (2 * ATILE)           // K, V
#define ATTN_SMEM (2 * ASTG)        // 36864

__global__ void __launch_bounds__(256) attn_f16_kernel(const int* __restrict__ mask)
{
    extern __shared__ char smem[];
    const uint32_t sb = smem_u32(smem);
    const int tid = threadIdx.x, lane = tid & 31, w = tid >> 5;
    const int bh = blockIdx.y, b = bh >> 4, h = bh & 15;
    const int bm = blockIdx.x * 128;

    const __half* q16 = g_q16 + (size_t)bh * SSZ * AD;
    const __half* k16 = g_k16 + (size_t)bh * SSZ * AD;
    const __half* v16 = g_v16 + (size_t)bh * SSZ * AD;

    // ---- load Q tile into stage0 area, pull frags to regs ----
    #pragma unroll
    for (int i = 0; i < 4; i++) {
        int unit = tid + i * 256;          // 0..1023
        int rr   = unit >> 3;
        int c16  = unit & 7;
        CP_ASYNC16(sb + rr * ARS + c16 * 16,
                   q16 + (size_t)(bm + rr) * AD + c16 * 8);
    }
    CP_COMMIT();
    CP_WAIT0();
    __syncthreads();

    uint32_t aq[4][4];
    {
        const uint32_t a_lane = (lane & 15) * ARS + (lane >> 4) * 16;
        #pragma unroll
        for (int ks = 0; ks < 4; ks++)
            LDSM_X4(aq[ks], sb + (w * 16) * ARS + a_lane + ks * 32);
    }
    __syncthreads();

    auto load_stage = [&](int t0, int st) {
        #pragma unroll
        for (int i = 0; i < 4; i++) {
            int unit = tid + i * 256;      // 0..1023
            int t    = unit >> 9;          // 0 = K, 1 = V
            int rr   = (unit >> 3) & 63;
            int c16  = unit & 7;
            const __half* src = t ? v16 : k16;
            CP_ASYNC16(sb + st * ASTG + t * ATILE + rr * ARS + c16 * 16,
                       src + (size_t)(t0 + rr) * AD + c16 * 8);
        }
    };

    float co[8][4];
    #pragma unroll
    for (int ni = 0; ni < 8; ni++)
        #pragma unroll
        for (int j = 0; j < 4; j++) co[ni][j] = 0.f;
    float mx0 = -1e30f, mx1 = -1e30f, l0 = 0.f, l1 = 0.f;

    const int qr = bm + w * 16 + (lane >> 2);
    const int* mrow0 = mask + ((size_t)b * SSZ + qr) * SSZ;
    const int* mrow1 = mrow0 + (size_t)8 * SSZ;
    const uint32_t b_lane = ((lane & 7) + ((lane >> 4) & 1) * 8) * ARS + ((lane >> 3) & 1) * 16;
    const uint32_t v_lane = ((lane & 7) + ((lane >> 3) & 1) * 8) * ARS + ((lane >> 4) & 1) * 16;

    load_stage(0, 0);
    CP_COMMIT();

    for (int t = 0; t < SSZ / 64; t++) {
        const int st = t & 1;
        if (t + 1 < SSZ / 64) load_stage((t + 1) * 64, st ^ 1);
        CP_COMMIT();

        // prefetch mask while cp.async completes
        const int kb = t * 64;
        int2 m0v[8], m1v[8];
        #pragma unroll
        for (int ni = 0; ni < 8; ni++) {
            const int key = kb + ni * 8 + (lane & 3) * 2;
            m0v[ni] = *(const int2*)(mrow0 + key);
            m1v[ni] = *(const int2*)(mrow1 + key);
        }

        CP_WAIT1();
        __syncthreads();

        const uint32_t sK = sb + st * ASTG;
        const uint32_t sV = sK + ATILE;

        // ---- scores S = Q K^T ----
        float s[8][4];
        #pragma unroll
        for (int ni = 0; ni < 8; ni++)
            #pragma unroll
            for (int j = 0; j < 4; j++) s[ni][j] = 0.f;

        #pragma unroll
        for (int ks = 0; ks < 4; ks++) {
            #pragma unroll
            for (int p = 0; p < 4; p++) {
                uint32_t kf[4];
                LDSM_X4(kf, sK + (p * 16) * ARS + b_lane + ks * 32);
                MMAF16(s[2*p],   aq[ks], kf[0], kf[1]);
                MMAF16(s[2*p+1], aq[ks], kf[2], kf[3]);
            }
        }

        // ---- mask ----
        #pragma unroll
        for (int ni = 0; ni < 8; ni++) {
            if (m0v[ni].x) s[ni][0] = -1e30f;
            if (m0v[ni].y) s[ni][1] = -1e30f;
            if (m1v[ni].x) s[ni][2] = -1e30f;
            if (m1v[ni].y) s[ni][3] = -1e30f;
        }

        // ---- online softmax ----
        float tm0 = -1e30f, tm1 = -1e30f;
        #pragma unroll
        for (int ni = 0; ni < 8; ni++) {
            tm0 = fmaxf(tm0, fmaxf(s[ni][0], s[ni][1]));
            tm1 = fmaxf(tm1, fmaxf(s[ni][2], s[ni][3]));
        }
        tm0 = fmaxf(tm0, __shfl_xor_sync(0xffffffffu, tm0, 1));
        tm0 = fmaxf(tm0, __shfl_xor_sync(0xffffffffu, tm0, 2));
        tm1 = fmaxf(tm1, __shfl_xor_sync(0xffffffffu, tm1, 1));
        tm1 = fmaxf(tm1, __shfl_xor_sync(0xffffffffu, tm1, 2));
        const float mn0 = fmaxf(mx0, tm0), mn1 = fmaxf(mx1, tm1);
        const float cr0 = __expf(mx0 - mn0), cr1 = __expf(mx1 - mn1);
        l0 *= cr0; l1 *= cr1;
        mx0 = mn0; mx1 = mn1;
        #pragma unroll
        for (int ni = 0; ni < 8; ni++) {
            s[ni][0] = __expf(s[ni][0] - mn0);
            s[ni][1] = __expf(s[ni][1] - mn0);
            s[ni][2] = __expf(s[ni][2] - mn1);
            s[ni][3] = __expf(s[ni][3] - mn1);
            l0 += s[ni][0] + s[ni][1];
            l1 += s[ni][2] + s[ni][3];
            co[ni][0] *= cr0; co[ni][1] *= cr0;
            co[ni][2] *= cr1; co[ni][3] *= cr1;
        }

        // ---- O += P V  (fp16 P, single pass) ----
        #pragma unroll
        for (int ks = 0; ks < 4; ks++) {
            uint32_t ph[4];
            PACK_F16X2(ph[0], s[2*ks][0],   s[2*ks][1]);
            PACK_F16X2(ph[1], s[2*ks][2],   s[2*ks][3]);
            PACK_F16X2(ph[2], s[2*ks+1][0], s[2*ks+1][1]);
            PACK_F16X2(ph[3], s[2*ks+1][2], s[2*ks+1][3]);
            #pragma unroll
            for (int p = 0; p < 4; p++) {
                uint32_t vf[4];
                LDSM_X4_T(vf, sV + (ks * 16) * ARS + p * 32 + v_lane);
                MMAF16(co[2*p],   ph, vf[0], vf[1]);
                MMAF16(co[2*p+1], ph, vf[2], vf[3]);
            }
        }
        __syncthreads();
    }

    // ---- epilogue: normalize, write fp16 [B,S,HID] ----
    l0 += __shfl_xor_sync(0xffffffffu, l0, 1);
    l0 += __shfl_xor_sync(0xffffffffu, l0, 2);
    l1 += __shfl_xor_sync(0xffffffffu, l1, 1);
    l1 += __shfl_xor_sync(0xffffffffu, l1, 2);
    const float i0 = 1.f / l0, i1 = 1.f / l1;

    const size_t d0 = ((size_t)b * SSZ + qr) * HID + h * AD;
    const size_t d1 = ((size_t)b * SSZ + qr + 8) * HID + h * AD;
    #pragma unroll
    for (int ni = 0; ni < 8; ni++) {
        const int dd = ni * 8 + (lane & 3) * 2;
        uint32_t u0, u1;
        PACK_F16X2(u0, co[ni][0] * i0, co[ni][1] * i0);
        PACK_F16X2(u1, co[ni][2] * i1, co[ni][3] * i1);
        *(uint32_t*)&g_o16[d0 + dd] = u0;
        *(uint32_t*)&g_o16[d1 + dd] = u1;
    }
}

// ============================================================
extern "C" void kernel_launch(void* const* d_in, const int* in_sizes, int n_in,
                              void* d_out, int out_size)
{
    const float* iQ   = (const float*)d_in[0];
    const int*   mask = (const int*)d_in[1];
    const float* Wa   = (const float*)d_in[2];
    const float* Wo   = (const float*)d_in[3];
    float*       out  = (float*)d_out;

    cudaFuncSetAttribute(gemm_f16_kernel,
                         cudaFuncAttributeMaxDynamicSharedMemorySize, GEMM_SMEM);
    cudaFuncSetAttribute(attn_f16_kernel,
                         cudaFuncAttributeMaxDynamicSharedMemorySize, ATTN_SMEM);

    __half *iQ16, *Wa16, *Wo16, *o16;
    cudaGetSymbolAddress((void**)&iQ16, g_iQ16);
    cudaGetSymbolAddress((void**)&Wa16, g_Wa16);
    cudaGetSymbolAddress((void**)&Wo16, g_Wo16);
    cudaGetSymbolAddress((void**)&o16, g_o16);

    // fp32 -> fp16 converts
    cvt_kernel<<<(BSZ * SSZ * DSZ) / 2048, 256>>>(iQ, iQ16);
    cvt_kernel<<<(3 * HID * DSZ) / 2048, 256>>>(Wa, Wa16);
    cvt_kernel<<<(HID * HID) / 2048, 256>>>(Wo, Wo16);

    // 1) QKV projection -> fp16 head-major Q(scaled)/K/V
    {
        dim3 grid(3 * HID / 128, (BSZ * SSZ) / 128);   // (24, 64)
        gemm_f16_kernel<<<grid, 256, GEMM_SMEM>>>(iQ16, Wa16, nullptr, 0);
    }
    // 2) attention -> fp16 O
    {
        dim3 grid(SSZ / 128, BSZ * HN);                // (16, 64)
        attn_f16_kernel<<<grid, 256, ATTN_SMEM>>>(mask);
    }
    // 3) output projection -> fp32 out
    {
        dim3 grid(HID / 128, (BSZ * SSZ) / 128);       // (8, 64)
        gemm_f16_kernel<<<grid, 256, GEMM_SMEM>>>(o16, Wo16, out, 1);
    }
}

// round 7
// speedup vs baseline: 8.7860x; 1.4050x over previous
#include <cuda_runtime.h>
#include <cuda_fp16.h>
#include <cstdint>

// Problem dims (fixed by reference)
#define BSZ 4
#define SSZ 2048
#define DSZ 1024
#define HN  16
#define AD  64
#define HID 1024
#define KTOT 1024

// ---------------- scratch (no allocs allowed) ----------------
__device__ __half g_iQ16[(size_t)BSZ * SSZ * DSZ];
__device__ __half g_Wa16[(size_t)3 * HID * DSZ];
__device__ __half g_Wo16[(size_t)HID * HID];
// head-major Q/K/V fp16  [B,H,S,AD]  (Q pre-scaled by 0.125*log2e)
__device__ __half g_q16[(size_t)BSZ * HN * SSZ * AD];
__device__ __half g_k16[(size_t)BSZ * HN * SSZ * AD];
__device__ __half g_v16[(size_t)BSZ * HN * SSZ * AD];
// attention output fp16  [B,S,HID]
__device__ __half g_o16[(size_t)BSZ * SSZ * HID];
// bit-packed mask [B,S,S/32]
__device__ uint32_t g_pm[(size_t)BSZ * SSZ * (SSZ / 32)];

// ---------------- PTX helpers ----------------
__device__ __forceinline__ uint32_t smem_u32(const void* p) {
    uint32_t a;
    asm("{ .reg .u64 t; cvta.to.shared.u64 t, %1; cvt.u32.u64 %0, t; }" : "=r"(a) : "l"(p));
    return a;
}
#define CP_ASYNC16(dst, src) \
    asm volatile("cp.async.cg.shared.global [%0], [%1], 16;" :: "r"(dst), "l"(src) : "memory")
#define CP_COMMIT() asm volatile("cp.async.commit_group;" ::: "memory")
#define CP_WAIT1()  asm volatile("cp.async.wait_group 1;" ::: "memory")
#define CP_WAIT0()  asm volatile("cp.async.wait_group 0;" ::: "memory")

#define LDSM_X4(r, addr) \
    asm volatile("ldmatrix.sync.aligned.m8n8.x4.shared.b16 {%0,%1,%2,%3}, [%4];" \
        : "=r"((r)[0]), "=r"((r)[1]), "=r"((r)[2]), "=r"((r)[3]) : "r"(addr))
#define LDSM_X4_T(r, addr) \
    asm volatile("ldmatrix.sync.aligned.m8n8.x4.trans.shared.b16 {%0,%1,%2,%3}, [%4];" \
        : "=r"((r)[0]), "=r"((r)[1]), "=r"((r)[2]), "=r"((r)[3]) : "r"(addr))

#define MMAF16(c, a, b0, b1) \
    asm volatile("mma.sync.aligned.m16n8k16.row.col.f32.f16.f16.f32 " \
        "{%0,%1,%2,%3}, {%4,%5,%6,%7}, {%8,%9}, {%0,%1,%2,%3};" \
        : "+f"((c)[0]), "+f"((c)[1]), "+f"((c)[2]), "+f"((c)[3]) \
        : "r"((a)[0]), "r"((a)[1]), "r"((a)[2]), "r"((a)[3]), "r"(b0), "r"(b1))

// pack two floats into f16x2 (flo -> low half, fhi -> high half)
#define PACK_F16X2(u, flo, fhi) \
    asm("cvt.rn.f16x2.f32 %0, %1, %2;" : "=r"(u) : "f"(fhi), "f"(flo))
// 2^x on fp16 pairs
#define EX2_F16X2(d, a) \
    asm("ex2.approx.f16x2 %0, %1;" : "=r"(d) : "r"(a))
#define EX2_F32(d, a) \
    asm("ex2.approx.ftz.f32 %0, %1;" : "=f"(d) : "f"(a))

#define QSCALE 0.1803368801111204f   // 0.125 * log2(e)

// ============================================================
// fp32 -> fp16 convert.  One thread = 8 elements.
// ============================================================
__global__ void __launch_bounds__(256) cvt_kernel(
    const float* __restrict__ src, __half* __restrict__ dst)
{
    size_t i = (size_t)blockIdx.x * 256 + threadIdx.x;
    float4 x0 = ((const float4*)src)[2 * i];
    float4 x1 = ((const float4*)src)[2 * i + 1];
    uint4 o;
    PACK_F16X2(o.x, x0.x, x0.y);
    PACK_F16X2(o.y, x0.z, x0.w);
    PACK_F16X2(o.z, x1.x, x1.y);
    PACK_F16X2(o.w, x1.z, x1.w);
    ((uint4*)dst)[i] = o;
}

// ============================================================
// int32 mask -> bit-packed mask.  One thread = one 32-bit word.
// ============================================================
__global__ void __launch_bounds__(256) mask_pack_kernel(
    const int* __restrict__ mask, uint32_t* __restrict__ pm)
{
    size_t w = (size_t)blockIdx.x * 256 + threadIdx.x;
    const int4* src = (const int4*)(mask + w * 32);
    uint32_t bits = 0;
    #pragma unroll
    for (int i = 0; i < 8; i++) {
        int4 v = src[i];
        bits |= (v.x ? 1u : 0u) << (4 * i);
        bits |= (v.y ? 1u : 0u) << (4 * i + 1);
        bits |= (v.z ? 1u : 0u) << (4 * i + 2);
        bits |= (v.w ? 1u : 0u) << (4 * i + 3);
    }
    pm[w] = bits;
}

// ============================================================
// fp16 single-pass GEMM: C[m,n] = sum_k A[m,k]*B[n,k]  (both K-major)
// Block 128x128, 8 warps (warp 32x64), BK=64 (144B padded rows), 2-stage.
// mode 0: epilogue -> fp16 head-major g_q16(scaled by QSCALE)/g_k16/g_v16.
// mode 1: fp32 store to Cplain.
// ============================================================
#define GRS    144
#define GTILE  (128 * GRS)
#define GSTAGE (2 * GTILE)
#define GEMM_SMEM (2 * GSTAGE)

__global__ void __launch_bounds__(256) gemm_f16_kernel(
    const __half* __restrict__ A, const __half* __restrict__ B,
    float* __restrict__ Cplain, int mode)
{
    extern __shared__ char smem[];
    const uint32_t sb = smem_u32(smem);
    const int tid  = threadIdx.x;
    const int lane = tid & 31;
    const int wid  = tid >> 5;
    const int wm   = wid & 3;
    const int wn   = wid >> 2;
    const int bm = blockIdx.y * 128;
    const int bn = blockIdx.x * 128;

    auto load_stage = [&](int ch, int st) {
        #pragma unroll
        for (int i = 0; i < 8; i++) {
            int unit = tid + i * 256;
            int t    = unit >> 10;
            int rr   = (unit >> 3) & 127;
            int c16  = unit & 7;
            const __half* src = t ? B : A;
            const int rowbase = t ? bn : bm;
            CP_ASYNC16(sb + st * GSTAGE + t * GTILE + rr * GRS + c16 * 16,
                       src + (size_t)(rowbase + rr) * KTOT + ch * 64 + c16 * 8);
        }
    };

    float c[2][8][4];
    #pragma unroll
    for (int mi = 0; mi < 2; mi++)
        #pragma unroll
        for (int ni = 0; ni < 8; ni++)
            #pragma unroll
            for (int j = 0; j < 4; j++) c[mi][ni][j] = 0.f;

    const uint32_t a_lane = (lane & 15) * GRS + (lane >> 4) * 16;
    const uint32_t b_lane = ((lane & 7) + ((lane >> 4) & 1) * 8) * GRS
                          + ((lane >> 3) & 1) * 16;

    load_stage(0, 0);
    CP_COMMIT();

    const int NCH = KTOT / 64;
    for (int ch = 0; ch < NCH; ch++) {
        const int st = ch & 1;
        if (ch + 1 < NCH) load_stage(ch + 1, st ^ 1);
        CP_COMMIT();
        CP_WAIT1();
        __syncthreads();

        const uint32_t sA = sb + st * GSTAGE;
        const uint32_t sB = sA + GTILE;

        #pragma unroll
        for (int ks = 0; ks < 4; ks++) {
            const uint32_t ak = ks * 32;
            uint32_t af[2][4], bf[4][4];
            #pragma unroll
            for (int mi = 0; mi < 2; mi++)
                LDSM_X4(af[mi], sA + (wm * 32 + mi * 16) * GRS + a_lane + ak);
            #pragma unroll
            for (int p = 0; p < 4; p++)
                LDSM_X4(bf[p], sB + (wn * 64 + p * 16) * GRS + b_lane + ak);
            #pragma unroll
            for (int mi = 0; mi < 2; mi++)
                #pragma unroll
                for (int p = 0; p < 4; p++) {
                    MMAF16(c[mi][2*p],   af[mi], bf[p][0], bf[p][1]);
                    MMAF16(c[mi][2*p+1], af[mi], bf[p][2], bf[p][3]);
                }
        }
        __syncthreads();
    }

    #pragma unroll
    for (int mi = 0; mi < 2; mi++) {
        const int r0 = bm + wm * 32 + mi * 16 + (lane >> 2);
        #pragma unroll
        for (int ni = 0; ni < 8; ni++) {
            const int ng = bn + wn * 64 + ni * 8 + (lane & 3) * 2;
            if (mode == 1) {
                float* d0 = Cplain + (size_t)r0 * HID + ng;
                float* d1 = Cplain + (size_t)(r0 + 8) * HID + ng;
                *(float2*)d0 = make_float2(c[mi][ni][0], c[mi][ni][1]);
                *(float2*)d1 = make_float2(c[mi][ni][2], c[mi][ni][3]);
            } else {
                const int which = ng >> 10;
                const int rr = ng & 1023;
                const int hh = rr >> 6;
                const int dd = rr & 63;
                const float sc = (which == 0) ? QSCALE : 1.f;
                __half* dst = (which == 0) ? g_q16 : ((which == 1) ? g_k16 : g_v16);
                #pragma unroll
                for (int half = 0; half < 2; half++) {
                    const int r = r0 + half * 8;
                    const int b = r >> 11, s = r & 2047;
                    size_t e = (((size_t)(b * HN + hh) * SSZ + s)) * AD + dd;
                    uint32_t u;
                    PACK_F16X2(u, c[mi][ni][half * 2] * sc, c[mi][ni][half * 2 + 1] * sc);
                    *(uint32_t*)&dst[e] = u;
                }
            }
        }
    }
}

// ============================================================
// Flash attention, fp16 mma, base-2 softmax with f16x2 MUFU exp.
// Block: 128 q-rows, 8 warps (16 rows each), KV tiles of 64, 2-stage.
// ============================================================
#define ARS   144
#define ATILE (64 * ARS)
#define ASTG  (2 * ATILE)
#define ATTN_SMEM (2 * ASTG)

__global__ void __launch_bounds__(256) attn_f16_kernel()
{
    extern __shared__ char smem[];
    const uint32_t sb = smem_u32(smem);
    const int tid = threadIdx.x, lane = tid & 31, w = tid >> 5;
    const int bh = blockIdx.y, b = bh >> 4, h = bh & 15;
    const int bm = blockIdx.x * 128;

    const __half* q16 = g_q16 + (size_t)bh * SSZ * AD;
    const __half* k16 = g_k16 + (size_t)bh * SSZ * AD;
    const __half* v16 = g_v16 + (size_t)bh * SSZ * AD;

    // ---- load Q tile, pull frags to regs ----
    #pragma unroll
    for (int i = 0; i < 4; i++) {
        int unit = tid + i * 256;
        int rr   = unit >> 3;
        int c16  = unit & 7;
        CP_ASYNC16(sb + rr * ARS + c16 * 16,
                   q16 + (size_t)(bm + rr) * AD + c16 * 8);
    }
    CP_COMMIT();
    CP_WAIT0();
    __syncthreads();

    uint32_t aq[4][4];
    {
        const uint32_t a_lane = (lane & 15) * ARS + (lane >> 4) * 16;
        #pragma unroll
        for (int ks = 0; ks < 4; ks++)
            LDSM_X4(aq[ks], sb + (w * 16) * ARS + a_lane + ks * 32);
    }
    __syncthreads();

    auto load_stage = [&](int t0, int st) {
        #pragma unroll
        for (int i = 0; i < 4; i++) {
            int unit = tid + i * 256;
            int t    = unit >> 9;
            int rr   = (unit >> 3) & 63;
            int c16  = unit & 7;
            const __half* src = t ? v16 : k16;
            CP_ASYNC16(sb + st * ASTG + t * ATILE + rr * ARS + c16 * 16,
                       src + (size_t)(t0 + rr) * AD + c16 * 8);
        }
    };

    float co[8][4];
    #pragma unroll
    for (int ni = 0; ni < 8; ni++)
        #pragma unroll
        for (int j = 0; j < 4; j++) co[ni][j] = 0.f;
    float mx0 = -1e30f, mx1 = -1e30f, l0 = 0.f, l1 = 0.f;

    const int qr = bm + w * 16 + (lane >> 2);
    const uint32_t* pr0 = g_pm + ((size_t)b * SSZ + qr) * (SSZ / 32);
    const uint32_t* pr1 = pr0 + (size_t)8 * (SSZ / 32);
    const int mbit = (lane & 3) * 2;   // bit base within byte-group
    const uint32_t b_lane = ((lane & 7) + ((lane >> 4) & 1) * 8) * ARS + ((lane >> 3) & 1) * 16;
    const uint32_t v_lane = ((lane & 7) + ((lane >> 3) & 1) * 8) * ARS + ((lane >> 4) & 1) * 16;

    load_stage(0, 0);
    CP_COMMIT();

    for (int t = 0; t < SSZ / 64; t++) {
        const int st = t & 1;
        if (t + 1 < SSZ / 64) load_stage((t + 1) * 64, st ^ 1);
        CP_COMMIT();

        // mask words for this tile (2 words per row cover 64 keys)
        uint2 mw0 = *(const uint2*)(pr0 + t * 2);
        uint2 mw1 = *(const uint2*)(pr1 + t * 2);

        CP_WAIT1();
        __syncthreads();

        const uint32_t sK = sb + st * ASTG;
        const uint32_t sV = sK + ATILE;

        // ---- scores S = Q K^T (log2-domain: Q pre-scaled by log2e/8) ----
        float s[8][4];
        #pragma unroll
        for (int ni = 0; ni < 8; ni++)
            #pragma unroll
            for (int j = 0; j < 4; j++) s[ni][j] = 0.f;

        #pragma unroll
        for (int ks = 0; ks < 4; ks++) {
            #pragma unroll
            for (int p = 0; p < 4; p++) {
                uint32_t kf[4];
                LDSM_X4(kf, sK + (p * 16) * ARS + b_lane + ks * 32);
                MMAF16(s[2*p],   aq[ks], kf[0], kf[1]);
                MMAF16(s[2*p+1], aq[ks], kf[2], kf[3]);
            }
        }

        // ---- mask via packed bits ----
        #pragma unroll
        for (int ni = 0; ni < 8; ni++) {
            const uint32_t w0 = (ni < 4) ? mw0.x : mw0.y;
            const uint32_t w1 = (ni < 4) ? mw1.x : mw1.y;
            const int sh = (ni & 3) * 8 + mbit;
            if ((w0 >> sh) & 1)       s[ni][0] = -1e30f;
            if ((w0 >> (sh + 1)) & 1) s[ni][1] = -1e30f;
            if ((w1 >> sh) & 1)       s[ni][2] = -1e30f;
            if ((w1 >> (sh + 1)) & 1) s[ni][3] = -1e30f;
        }

        // ---- online softmax (base-2) ----
        float tm0 = -1e30f, tm1 = -1e30f;
        #pragma unroll
        for (int ni = 0; ni < 8; ni++) {
            tm0 = fmaxf(tm0, fmaxf(s[ni][0], s[ni][1]));
            tm1 = fmaxf(tm1, fmaxf(s[ni][2], s[ni][3]));
        }
        tm0 = fmaxf(tm0, __shfl_xor_sync(0xffffffffu, tm0, 1));
        tm0 = fmaxf(tm0, __shfl_xor_sync(0xffffffffu, tm0, 2));
        tm1 = fmaxf(tm1, __shfl_xor_sync(0xffffffffu, tm1, 1));
        tm1 = fmaxf(tm1, __shfl_xor_sync(0xffffffffu, tm1, 2));
        const float mn0 = fmaxf(mx0, tm0), mn1 = fmaxf(mx1, tm1);
        float cr0, cr1;
        EX2_F32(cr0, mx0 - mn0);
        EX2_F32(cr1, mx1 - mn1);
        l0 *= cr0; l1 *= cr1;
        mx0 = mn0; mx1 = mn1;

        // p = 2^(s-m), pairwise in f16x2 — result is directly the PV A-frag
        uint32_t plo[8], phi[8];
        #pragma unroll
        for (int ni = 0; ni < 8; ni++) {
            uint32_t d0, d1;
            PACK_F16X2(d0, s[ni][0] - mn0, s[ni][1] - mn0);
            PACK_F16X2(d1, s[ni][2] - mn1, s[ni][3] - mn1);
            EX2_F16X2(plo[ni], d0);
            EX2_F16X2(phi[ni], d1);
            co[ni][0] *= cr0; co[ni][1] *= cr0;
            co[ni][2] *= cr1; co[ni][3] *= cr1;
        }

        // l += sum(p) via HADD2 trees (fp16 partial sums -> fp32)
        {
            __half2 a0 = *(__half2*)&plo[0];
            #pragma unroll
            for (int ni = 1; ni < 8; ni++) a0 = __hadd2(a0, *(__half2*)&plo[ni]);
            __half2 a1 = *(__half2*)&phi[0];
            #pragma unroll
            for (int ni = 1; ni < 8; ni++) a1 = __hadd2(a1, *(__half2*)&phi[ni]);
            float2 f0 = __half22float2(a0);
            float2 f1 = __half22float2(a1);
            l0 += f0.x + f0.y;
            l1 += f1.x + f1.y;
        }

        // ---- O += P V ----
        #pragma unroll
        for (int ks = 0; ks < 4; ks++) {
            uint32_t ph[4] = {plo[2*ks], phi[2*ks], plo[2*ks+1], phi[2*ks+1]};
            #pragma unroll
            for (int p = 0; p < 4; p++) {
                uint32_t vf[4];
                LDSM_X4_T(vf, sV + (ks * 16) * ARS + p * 32 + v_lane);
                MMAF16(co[2*p],   ph, vf[0], vf[1]);
                MMAF16(co[2*p+1], ph, vf[2], vf[3]);
            }
        }
        __syncthreads();
    }

    // ---- epilogue: normalize, write fp16 [B,S,HID] ----
    l0 += __shfl_xor_sync(0xffffffffu, l0, 1);
    l0 += __shfl_xor_sync(0xffffffffu, l0, 2);
    l1 += __shfl_xor_sync(0xffffffffu, l1, 1);
    l1 += __shfl_xor_sync(0xffffffffu, l1, 2);
    const float i0 = 1.f / l0, i1 = 1.f / l1;

    const size_t d0 = ((size_t)b * SSZ + qr) * HID + h * AD;
    const size_t d1 = ((size_t)b * SSZ + qr + 8) * HID + h * AD;
    #pragma unroll
    for (int ni = 0; ni < 8; ni++) {
        const int dd = ni * 8 + (lane & 3) * 2;
        uint32_t u0, u1;
        PACK_F16X2(u0, co[ni][0] * i0, co[ni][1] * i0);
        PACK_F16X2(u1, co[ni][2] * i1, co[ni][3] * i1);
        *(uint32_t*)&g_o16[d0 + dd] = u0;
        *(uint32_t*)&g_o16[d1 + dd] = u1;
    }
}

// ============================================================
extern "C" void kernel_launch(void* const* d_in, const int* in_sizes, int n_in,
                              void* d_out, int out_size)
{
    const float* iQ   = (const float*)d_in[0];
    const int*   mask = (const int*)d_in[1];
    const float* Wa   = (const float*)d_in[2];
    const float* Wo   = (const float*)d_in[3];
    float*       out  = (float*)d_out;

    cudaFuncSetAttribute(gemm_f16_kernel,
                         cudaFuncAttributeMaxDynamicSharedMemorySize, GEMM_SMEM);
    cudaFuncSetAttribute(attn_f16_kernel,
                         cudaFuncAttributeMaxDynamicSharedMemorySize, ATTN_SMEM);

    __half *iQ16, *Wa16, *Wo16, *o16;
    uint32_t* pm;
    cudaGetSymbolAddress((void**)&iQ16, g_iQ16);
    cudaGetSymbolAddress((void**)&Wa16, g_Wa16);
    cudaGetSymbolAddress((void**)&Wo16, g_Wo16);
    cudaGetSymbolAddress((void**)&o16, g_o16);
    cudaGetSymbolAddress((void**)&pm, g_pm);

    // fp32 -> fp16 converts + mask bit-pack
    cvt_kernel<<<(BSZ * SSZ * DSZ) / 2048, 256>>>(iQ, iQ16);
    cvt_kernel<<<(3 * HID * DSZ) / 2048, 256>>>(Wa, Wa16);
    cvt_kernel<<<(HID * HID) / 2048, 256>>>(Wo, Wo16);
    mask_pack_kernel<<<((size_t)BSZ * SSZ * SSZ / 32) / 256, 256>>>(mask, pm);

    // 1) QKV projection -> fp16 head-major Q(scaled)/K/V
    {
        dim3 grid(3 * HID / 128, (BSZ * SSZ) / 128);   // (24, 64)
        gemm_f16_kernel<<<grid, 256, GEMM_SMEM>>>(iQ16, Wa16, nullptr, 0);
    }
    // 2) attention -> fp16 O
    {
        dim3 grid(SSZ / 128, BSZ * HN);                // (16, 64)
        attn_f16_kernel<<<grid, 256, ATTN_SMEM>>>();
    }
    // 3) output projection -> fp32 out
    {
        dim3 grid(HID / 128, (BSZ * SSZ) / 128);       // (8, 64)
        gemm_f16_kernel<<<grid, 256, GEMM_SMEM>>>(o16, Wo16, out, 1);
    }
}